// round 4
// baseline (speedup 1.0000x reference)
#include <cuda_runtime.h>
#include <math_constants.h>

#define GRID_MAX 2048
__device__ float    g_partial[GRID_MAX];  // per-block running max (plain store, no init)
__device__ unsigned g_count;              // zero at load; last block resets to 0 each call

__device__ __forceinline__ void top2_update(float& t1, float& t2, float v) {
    t2 = fmaxf(t2, fminf(t1, v));
    t1 = fmaxf(t1, v);
}

// Persistent kernel: 256 threads (warps 0..6 active per row). Each block
// grid-strides over rows; per-row body identical to the R3 winner.
// Tail: last block reduces g_partial -> out_max[0], resets counter.
template<int NV4>   // NV4 = C/4
__global__ __launch_bounds__(256) void margin_softmax_fused(
    const float* __restrict__ o1, const float* __restrict__ o2,
    const float* __restrict__ o3, const float* __restrict__ o4,
    const float* __restrict__ o5, const float* __restrict__ o6,
    const float* __restrict__ mimic,
    const int* __restrict__ targets,
    float* __restrict__ out_thresh,   // [N,7]
    float* __restrict__ out_max,      // out[0]
    int C, int N)
{
    const int wid  = threadIdx.x >> 5;
    const int lane = threadIdx.x & 31;

    __shared__ float s_margin[7];
    __shared__ float s_top1[7];
    __shared__ float s_red[8];

    const float* heads[7] = {o1, o2, o3, o4, o5, o6, mimic};

    float blockmax = -CUDART_INF_F;

    for (int row = blockIdx.x; row < N; row += gridDim.x) {
        if (wid < 7) {
            const float* p = heads[wid] + (size_t)row * (size_t)C;
            const float4* p4 = (const float4*)p;

            constexpr int K = (NV4 + 31) / 32;   // 8 for NV4=250
            float4 v[K];
            #pragma unroll
            for (int k = 0; k < K; ++k) {
                int idx = lane + 32 * k;
                if (32 * k + 31 < NV4 || idx < NV4)
                    v[k] = p4[idx];
                else
                    v[k] = make_float4(-CUDART_INF_F, -CUDART_INF_F,
                                       -CUDART_INF_F, -CUDART_INF_F);
            }

            float t1 = -CUDART_INF_F, t2 = -CUDART_INF_F;
            #pragma unroll
            for (int k = 0; k < K; ++k) {
                top2_update(t1, t2, v[k].x);
                top2_update(t1, t2, v[k].y);
                top2_update(t1, t2, v[k].z);
                top2_update(t1, t2, v[k].w);
            }

            #pragma unroll
            for (int off = 16; off; off >>= 1) {
                float u1 = __shfl_down_sync(0xFFFFFFFFu, t1, off);
                float u2 = __shfl_down_sync(0xFFFFFFFFu, t2, off);
                t2 = fmaxf(fmaxf(t2, u2), fminf(t1, u1));
                t1 = fmaxf(t1, u1);
            }

            if (lane == 0) {
                float tval = __ldg(p + targets[row]);
                s_margin[wid] = (tval == t1) ? (t1 - t2) : 0.0f;
                s_top1[wid]   = t1;
            }
        }
        __syncthreads();

        if (threadIdx.x == 0) {
            float bm = s_top1[0];
            #pragma unroll
            for (int h = 1; h < 6; ++h) bm = fmaxf(bm, s_top1[h]);
            blockmax = fmaxf(blockmax, bm);

            float m[7], mx = -CUDART_INF_F;
            #pragma unroll
            for (int h = 0; h < 7; ++h) { m[h] = s_margin[h] * 0.5f; mx = fmaxf(mx, m[h]); }
            float e[7], sum = 0.0f;
            #pragma unroll
            for (int h = 0; h < 7; ++h) { e[h] = __expf(m[h] - mx); sum += e[h]; }
            float inv = 1.0f / sum;
            float* o = out_thresh + (size_t)row * 7;
            #pragma unroll
            for (int h = 0; h < 7; ++h) o[h] = e[h] * inv;
        }
        __syncthreads();
    }

    // ---- fused global-max tail (last-block-done pattern) ----
    __shared__ bool s_last;
    if (threadIdx.x == 0) {
        g_partial[blockIdx.x] = blockmax;
        __threadfence();
        unsigned old = atomicAdd(&g_count, 1u);
        s_last = (old == gridDim.x - 1);
    }
    __syncthreads();

    if (s_last) {
        float m = -CUDART_INF_F;
        for (unsigned i = threadIdx.x; i < gridDim.x; i += blockDim.x)
            m = fmaxf(m, g_partial[i]);
        #pragma unroll
        for (int off = 16; off; off >>= 1)
            m = fmaxf(m, __shfl_down_sync(0xFFFFFFFFu, m, off));
        if (lane == 0) s_red[wid] = m;
        __syncthreads();
        if (threadIdx.x < 8) {
            m = s_red[threadIdx.x];
            #pragma unroll
            for (int off = 4; off; off >>= 1)
                m = fmaxf(m, __shfl_down_sync(0xFFu, m, off));
            if (threadIdx.x == 0) {
                out_max[0] = m;
                g_count = 0;   // deterministic reset for next graph replay
            }
        }
    }
}

// Generic fallback (runtime C), same structure.
__global__ __launch_bounds__(256) void margin_softmax_fused_gen(
    const float* __restrict__ o1, const float* __restrict__ o2,
    const float* __restrict__ o3, const float* __restrict__ o4,
    const float* __restrict__ o5, const float* __restrict__ o6,
    const float* __restrict__ mimic,
    const int* __restrict__ targets,
    float* __restrict__ out_thresh, float* __restrict__ out_max,
    int C, int N)
{
    const int wid  = threadIdx.x >> 5;
    const int lane = threadIdx.x & 31;

    __shared__ float s_margin[7];
    __shared__ float s_top1[7];
    __shared__ float s_red[8];

    const float* heads[7] = {o1, o2, o3, o4, o5, o6, mimic};
    float blockmax = -CUDART_INF_F;

    for (int row = blockIdx.x; row < N; row += gridDim.x) {
        if (wid < 7) {
            const float* p = heads[wid] + (size_t)row * (size_t)C;
            float t1 = -CUDART_INF_F, t2 = -CUDART_INF_F;
            const int nv4 = C >> 2;
            const float4* p4 = (const float4*)p;
            for (int i = lane; i < nv4; i += 32) {
                float4 v = p4[i];
                top2_update(t1, t2, v.x); top2_update(t1, t2, v.y);
                top2_update(t1, t2, v.z); top2_update(t1, t2, v.w);
            }
            for (int i = (nv4 << 2) + lane; i < C; i += 32)
                top2_update(t1, t2, p[i]);

            #pragma unroll
            for (int off = 16; off; off >>= 1) {
                float u1 = __shfl_down_sync(0xFFFFFFFFu, t1, off);
                float u2 = __shfl_down_sync(0xFFFFFFFFu, t2, off);
                t2 = fmaxf(fmaxf(t2, u2), fminf(t1, u1));
                t1 = fmaxf(t1, u1);
            }
            if (lane == 0) {
                float tval = __ldg(p + targets[row]);
                s_margin[wid] = (tval == t1) ? (t1 - t2) : 0.0f;
                s_top1[wid]   = t1;
            }
        }
        __syncthreads();

        if (threadIdx.x == 0) {
            float bm = s_top1[0];
            #pragma unroll
            for (int h = 1; h < 6; ++h) bm = fmaxf(bm, s_top1[h]);
            blockmax = fmaxf(blockmax, bm);

            float m[7], mx = -CUDART_INF_F;
            #pragma unroll
            for (int h = 0; h < 7; ++h) { m[h] = s_margin[h] * 0.5f; mx = fmaxf(mx, m[h]); }
            float e[7], sum = 0.0f;
            #pragma unroll
            for (int h = 0; h < 7; ++h) { e[h] = __expf(m[h] - mx); sum += e[h]; }
            float inv = 1.0f / sum;
            float* o = out_thresh + (size_t)row * 7;
            #pragma unroll
            for (int h = 0; h < 7; ++h) o[h] = e[h] * inv;
        }
        __syncthreads();
    }

    __shared__ bool s_last;
    if (threadIdx.x == 0) {
        g_partial[blockIdx.x] = blockmax;
        __threadfence();
        unsigned old = atomicAdd(&g_count, 1u);
        s_last = (old == gridDim.x - 1);
    }
    __syncthreads();

    if (s_last) {
        float m = -CUDART_INF_F;
        for (unsigned i = threadIdx.x; i < gridDim.x; i += blockDim.x)
            m = fmaxf(m, g_partial[i]);
        #pragma unroll
        for (int off = 16; off; off >>= 1)
            m = fmaxf(m, __shfl_down_sync(0xFFFFFFFFu, m, off));
        if (lane == 0) s_red[wid] = m;
        __syncthreads();
        if (threadIdx.x < 8) {
            m = s_red[threadIdx.x];
            #pragma unroll
            for (int off = 4; off; off >>= 1)
                m = fmaxf(m, __shfl_down_sync(0xFFu, m, off));
            if (threadIdx.x == 0) { out_max[0] = m; g_count = 0; }
        }
    }
}

extern "C" void kernel_launch(void* const* d_in, const int* in_sizes, int n_in,
                              void* d_out, int out_size) {
    const float* o1    = (const float*)d_in[0];
    const float* o2    = (const float*)d_in[1];
    const float* o3    = (const float*)d_in[2];
    const float* o4    = (const float*)d_in[3];
    const float* o5    = (const float*)d_in[4];
    const float* o6    = (const float*)d_in[5];
    const float* mimic = (const float*)d_in[6];
    const int*   tgt   = (const int*)d_in[7];

    const int N = in_sizes[7];            // 16384 rows
    const int C = in_sizes[0] / N;        // 1000 classes

    float* out = (float*)d_out;           // [0]=max_preds, [1..]=thresholds [N,7]

    int grid = 1184;                      // 148 SMs x 8 CTAs
    if (grid > N) grid = N;
    if (grid > GRID_MAX) grid = GRID_MAX;

    if (C == 1000) {
        margin_softmax_fused<250><<<grid, 256>>>(o1, o2, o3, o4, o5, o6, mimic, tgt,
                                                 out + 1, out, C, N);
    } else {
        margin_softmax_fused_gen<<<grid, 256>>>(o1, o2, o3, o4, o5, o6, mimic, tgt,
                                                out + 1, out, C, N);
    }
}